// round 1
// baseline (speedup 1.0000x reference)
#include <cuda_runtime.h>

// ---------------------------------------------------------------------------
// Spikformer spatial+temporal SSA, fp32 SIMT implementation.
// Key exploits:
//  - LIF outputs are exactly binary -> spikes stored as {0,1} floats.
//  - attention (q k^T) v == q (k^T v) exactly (integer arithmetic in fp32).
//  - spike thresholds: conv: z*g+b >= 2 ; attention: integer count >= 8.
// ---------------------------------------------------------------------------

#define TT 10
#define BB 4
#define CC 384
#define NN 384
#define HH 12
#define CN (CC * NN)             // 147456
#define TBCN (TT * BB * CC * NN) // 5898240
#define BCN (BB * CC * NN)       // 589824

// scratch (static device globals; no allocation anywhere)
__device__ float g_q[TBCN];
__device__ float g_k[TBCN];
__device__ float g_v[TBCN];
__device__ float g_os[TBCN];   // attention-output spikes (t,b,c,n)
__device__ float g_a[TBCN];    // final conv spikes (reused: spatial a, then temporal bt)
__device__ float g_tq[TBCN];   // temporal-gathered layout [(n*B+b)*H+h][t*32+e]
__device__ float g_tk[TBCN];
__device__ float g_tv[TBCN];
__device__ float g_ared[TT * BB * CC];
__device__ float g_bred[BCN];

// ---------------------------------------------------------------------------
// Fused GEMM + BN + spike:  out[o,n] = ((sum_c W[o,c]*X[c,n])*g[o]+b[o] >= 2)
// 128x128 tile, BK=16, 256 threads, 8x8 microtile, double-buffered smem.
// 384 = 3*128, K=384 = 24*16 -> no bounds checks needed.
// ---------------------------------------------------------------------------
#define BM 128
#define BNb 128
#define BK 16
#define KT (CC / BK) // 24

__device__ __forceinline__ void gemm_spike_body(
    const float* __restrict__ W, const float* __restrict__ gs,
    const float* __restrict__ bs, const float* __restrict__ Xb,
    float* __restrict__ Ob)
{
    __shared__ float As[2][BK][BM];
    __shared__ float Bs[2][BK][BNb];

    const int tid = threadIdx.x;
    const int o0 = blockIdx.y * BM;
    const int n0 = blockIdx.x * BNb;

    // loader mapping
    const int a_oo = tid >> 2;          // 0..63
    const int a_k4 = (tid & 3) << 2;    // 0,4,8,12
    const int b_kk = tid >> 5;          // 0..7
    const int b_nf = (tid & 31) << 2;   // 0..124

    const float* Ap = W + (o0 + a_oo) * CC + a_k4;
    const float* Bp = Xb + b_kk * NN + n0 + b_nf;

    float4 ar0 = *(const float4*)(Ap);
    float4 ar1 = *(const float4*)(Ap + 64 * CC);
    float4 br0 = *(const float4*)(Bp);
    float4 br1 = *(const float4*)(Bp + 8 * NN);

    As[0][a_k4 + 0][a_oo] = ar0.x;
    As[0][a_k4 + 1][a_oo] = ar0.y;
    As[0][a_k4 + 2][a_oo] = ar0.z;
    As[0][a_k4 + 3][a_oo] = ar0.w;
    As[0][a_k4 + 0][a_oo + 64] = ar1.x;
    As[0][a_k4 + 1][a_oo + 64] = ar1.y;
    As[0][a_k4 + 2][a_oo + 64] = ar1.z;
    As[0][a_k4 + 3][a_oo + 64] = ar1.w;
    *(float4*)&Bs[0][b_kk][b_nf] = br0;
    *(float4*)&Bs[0][b_kk + 8][b_nf] = br1;
    __syncthreads();

    float acc[8][8];
#pragma unroll
    for (int i = 0; i < 8; ++i)
#pragma unroll
        for (int j = 0; j < 8; ++j) acc[i][j] = 0.0f;

    const int ao = (tid >> 4) << 3; // 0..120
    const int bn = (tid & 15) << 3; // 0..120

    for (int kt = 0; kt < KT; ++kt) {
        const int cur = kt & 1;
        if (kt + 1 < KT) {
            const float* Ap2 = Ap + (kt + 1) * BK;
            const float* Bp2 = Bp + (kt + 1) * BK * NN;
            ar0 = *(const float4*)(Ap2);
            ar1 = *(const float4*)(Ap2 + 64 * CC);
            br0 = *(const float4*)(Bp2);
            br1 = *(const float4*)(Bp2 + 8 * NN);
        }
#pragma unroll
        for (int kk = 0; kk < BK; ++kk) {
            float a[8], b[8];
            *(float4*)(a)     = *(const float4*)&As[cur][kk][ao];
            *(float4*)(a + 4) = *(const float4*)&As[cur][kk][ao + 4];
            *(float4*)(b)     = *(const float4*)&Bs[cur][kk][bn];
            *(float4*)(b + 4) = *(const float4*)&Bs[cur][kk][bn + 4];
#pragma unroll
            for (int i = 0; i < 8; ++i)
#pragma unroll
                for (int j = 0; j < 8; ++j)
                    acc[i][j] = fmaf(a[i], b[j], acc[i][j]);
        }
        if (kt + 1 < KT) {
            const int nxt = cur ^ 1;
            As[nxt][a_k4 + 0][a_oo] = ar0.x;
            As[nxt][a_k4 + 1][a_oo] = ar0.y;
            As[nxt][a_k4 + 2][a_oo] = ar0.z;
            As[nxt][a_k4 + 3][a_oo] = ar0.w;
            As[nxt][a_k4 + 0][a_oo + 64] = ar1.x;
            As[nxt][a_k4 + 1][a_oo + 64] = ar1.y;
            As[nxt][a_k4 + 2][a_oo + 64] = ar1.z;
            As[nxt][a_k4 + 3][a_oo + 64] = ar1.w;
            *(float4*)&Bs[nxt][b_kk][b_nf] = br0;
            *(float4*)&Bs[nxt][b_kk + 8][b_nf] = br1;
        }
        __syncthreads();
    }

#pragma unroll
    for (int i = 0; i < 8; ++i) {
        const int o = o0 + ao + i;
        const float gv = gs[o];
        const float bv = bs[o];
        float4 r0, r1;
        r0.x = (fmaf(acc[i][0], gv, bv) >= 2.0f) ? 1.0f : 0.0f;
        r0.y = (fmaf(acc[i][1], gv, bv) >= 2.0f) ? 1.0f : 0.0f;
        r0.z = (fmaf(acc[i][2], gv, bv) >= 2.0f) ? 1.0f : 0.0f;
        r0.w = (fmaf(acc[i][3], gv, bv) >= 2.0f) ? 1.0f : 0.0f;
        r1.x = (fmaf(acc[i][4], gv, bv) >= 2.0f) ? 1.0f : 0.0f;
        r1.y = (fmaf(acc[i][5], gv, bv) >= 2.0f) ? 1.0f : 0.0f;
        r1.z = (fmaf(acc[i][6], gv, bv) >= 2.0f) ? 1.0f : 0.0f;
        r1.w = (fmaf(acc[i][7], gv, bv) >= 2.0f) ? 1.0f : 0.0f;
        float* dst = Ob + (size_t)o * NN + n0 + bn;
        *(float4*)(dst) = r0;
        *(float4*)(dst + 4) = r1;
    }
}

// qkv projections fused in one launch: grid (3,3,120), z = j*40 + tb
__global__ void __launch_bounds__(256) k_qkv_gemm(
    const float* __restrict__ W4, const float* __restrict__ g4,
    const float* __restrict__ b4, const float* __restrict__ x,
    const float* __restrict__ y)
{
    const int z = blockIdx.z;
    const int j = z / (TT * BB);
    const int tb = z - j * (TT * BB);
    const float* W = W4 + j * CC * CC;
    const float* gs = g4 + j * CC;
    const float* bs = b4 + j * CC;
    const float* Xb = ((j == 0) ? x : y) + (size_t)tb * CN;
    float* Ob = ((j == 0) ? g_q : (j == 1) ? g_k : g_v) + (size_t)tb * CN;
    gemm_spike_body(W, gs, bs, Xb, Ob);
}

// final conv (W[3]) on attention-output spikes: grid (3,3,40)
__global__ void __launch_bounds__(256) k_final_gemm(
    const float* __restrict__ W, const float* __restrict__ gs,
    const float* __restrict__ bs)
{
    const int tb = blockIdx.z;
    gemm_spike_body(W, gs, bs, g_os + (size_t)tb * CN, g_a + (size_t)tb * CN);
}

// ---------------------------------------------------------------------------
// Spatial attention, per (t,b,h):  M = k^T v (32x32 integer), o = q M, spike o>=8
// grid = T*B*H = 480, 256 threads.
// ---------------------------------------------------------------------------
__global__ void __launch_bounds__(256) k_spatial_attn()
{
    __shared__ float ks[64][33];
    __shared__ float vs[64][33];
    __shared__ float Ms[32][33];

    const int blk = blockIdx.x;
    const int tb = blk / HH;
    const int h = blk - tb * HH;
    const size_t base = (size_t)tb * CN + (size_t)h * 32 * NN;
    const float* qb = g_q + base;
    const float* kb = g_k + base;
    const float* vb = g_v + base;
    float* ob = g_os + base;
    const int tid = threadIdx.x;

    // Phase 1: M[e][dd] = sum_m k[m,e]*v[m,dd]
    const int e = tid >> 3;            // 0..31
    const int dd0 = (tid & 7) << 2;    // 0..28
    float mc0 = 0.f, mc1 = 0.f, mc2 = 0.f, mc3 = 0.f;
    for (int m0 = 0; m0 < NN; m0 += 64) {
#pragma unroll
        for (int i = 0; i < 8; ++i) {
            int idx = tid + i * 256;
            int ee = idx >> 6, mm = idx & 63;
            ks[mm][ee] = kb[(size_t)ee * NN + m0 + mm];
            vs[mm][ee] = vb[(size_t)ee * NN + m0 + mm];
        }
        __syncthreads();
#pragma unroll 8
        for (int mm = 0; mm < 64; ++mm) {
            float kv = ks[mm][e];
            mc0 = fmaf(kv, vs[mm][dd0 + 0], mc0);
            mc1 = fmaf(kv, vs[mm][dd0 + 1], mc1);
            mc2 = fmaf(kv, vs[mm][dd0 + 2], mc2);
            mc3 = fmaf(kv, vs[mm][dd0 + 3], mc3);
        }
        __syncthreads();
    }
    Ms[e][dd0 + 0] = mc0;
    Ms[e][dd0 + 1] = mc1;
    Ms[e][dd0 + 2] = mc2;
    Ms[e][dd0 + 3] = mc3;
    __syncthreads();

    // Phase 2: o[n,dd] = sum_e q[n,e]*M[e,dd], spike >= 8 (exact integers)
    const int n_lane = tid & 63;
    const int d0 = (tid >> 6) << 3; // 0,8,16,24
    for (int n0 = 0; n0 < NN; n0 += 64) {
#pragma unroll
        for (int i = 0; i < 8; ++i) {
            int idx = tid + i * 256;
            int ee = idx >> 6, nn = idx & 63;
            ks[nn][ee] = qb[(size_t)ee * NN + n0 + nn]; // reuse ks as q-tile
        }
        __syncthreads();
        float oa[8];
#pragma unroll
        for (int j = 0; j < 8; ++j) oa[j] = 0.f;
#pragma unroll
        for (int ee = 0; ee < 32; ++ee) {
            float qv = ks[n_lane][ee];
#pragma unroll
            for (int j = 0; j < 8; ++j) oa[j] = fmaf(qv, Ms[ee][d0 + j], oa[j]);
        }
#pragma unroll
        for (int j = 0; j < 8; ++j)
            ob[(size_t)(d0 + j) * NN + n0 + n_lane] = (oa[j] >= 8.0f) ? 1.0f : 0.0f;
        __syncthreads();
    }
}

// ---------------------------------------------------------------------------
// Gather spikes into temporal layout: dst[((n*B+b)*H+h)*320 + t*32 + e]
// grid = 3 * 480 * 12 = 17280 (tensor, tbh, ntile), 256 threads, 32x32 transpose
// ---------------------------------------------------------------------------
__global__ void __launch_bounds__(256) k_gather_temporal()
{
    const int bx = blockIdx.x;
    const int which = bx / 5760;
    const int r = bx - which * 5760;
    const int ntile = r % 12;
    const int tbh = r / 12;
    const int tb = tbh / 12;
    const int h = tbh - tb * 12;
    const int t = tb / BB;
    const int b = tb - t * BB;

    const float* srcbase = (which == 0) ? g_q : (which == 1) ? g_k : g_v;
    float* dst = (which == 0) ? g_tq : (which == 1) ? g_tk : g_tv;
    const float* src = srcbase + (size_t)tb * CN + (size_t)h * 32 * NN + ntile * 32;

    __shared__ float tile[32][33];
    const int tid = threadIdx.x;
#pragma unroll
    for (int i = 0; i < 4; ++i) {
        int idx = tid + i * 256;
        int ee = idx >> 5, nn = idx & 31;
        tile[ee][nn] = src[(size_t)ee * NN + nn];
    }
    __syncthreads();
#pragma unroll
    for (int i = 0; i < 4; ++i) {
        int idx = tid + i * 256;
        int nn = idx >> 5, ee = idx & 31;
        int n = ntile * 32 + nn;
        dst[((size_t)(n * BB + b) * HH + h) * 320 + t * 32 + ee] = tile[ee][nn];
    }
}

// ---------------------------------------------------------------------------
// Temporal attention per (n,b,h): attn (10x10), o = attn v, spike >= 8,
// scatter through the torch reshape shuffle flat = h*320+t*32+dd -> (t',c').
// 8 groups (warps) per block; grid = 18432/8 = 2304.
// ---------------------------------------------------------------------------
__global__ void __launch_bounds__(256) k_temporal_attn()
{
    __shared__ float qs[8][321];   // transposed [e*10+t]
    __shared__ float ks2[8][321];  // transposed [e*10+s]
    __shared__ float vs2[8][321];  // natural    [s*32+dd]
    __shared__ float at[8][112];   // attn[t*10+s]

    const int wid = threadIdx.x >> 5;
    const int lane = threadIdx.x & 31;
    const int nbh = blockIdx.x * 8 + wid; // (n*B+b)*H+h
    const int h = nbh % HH;
    const int nb = nbh / HH;
    const int b = nb % BB;
    const int n = nb / BB;

    const float* qg = g_tq + (size_t)nbh * 320;
    const float* kg = g_tk + (size_t)nbh * 320;
    const float* vg = g_tv + (size_t)nbh * 320;

#pragma unroll
    for (int i = 0; i < TT; ++i) {
        qs[wid][lane * TT + i] = qg[i * 32 + lane];
        ks2[wid][lane * TT + i] = kg[i * 32 + lane];
        vs2[wid][i * 32 + lane] = vg[i * 32 + lane];
    }
    __syncwarp();

    for (int ii = lane; ii < 100; ii += 32) {
        int t = ii / 10, s = ii - t * 10;
        float acc = 0.f;
#pragma unroll
        for (int ee = 0; ee < 32; ++ee)
            acc = fmaf(qs[wid][ee * TT + t], ks2[wid][ee * TT + s], acc);
        at[wid][ii] = acc;
    }
    __syncwarp();

#pragma unroll
    for (int t = 0; t < TT; ++t) {
        float acc = 0.f;
#pragma unroll
        for (int s = 0; s < TT; ++s)
            acc = fmaf(at[wid][t * 10 + s], vs2[wid][s * 32 + lane], acc);
        float sp = (acc >= 8.0f) ? 1.0f : 0.0f;
        int flat = h * 320 + t * 32 + lane;
        int tp = flat / 384;
        int cp = flat - tp * 384;
        g_os[((size_t)(tp * BB + b) * CC + cp) * NN + n] = sp;
    }
}

// ---------------------------------------------------------------------------
// reductions + outer product
// ---------------------------------------------------------------------------
__global__ void __launch_bounds__(256) k_reduce_a() // 1920 blocks: 8 rows/block
{
    const int row = blockIdx.x * 8 + (threadIdx.x >> 5);
    const int lane = threadIdx.x & 31;
    const float* p = g_a + (size_t)row * NN;
    float s = 0.f;
#pragma unroll
    for (int i = lane; i < NN; i += 32) s += p[i];
#pragma unroll
    for (int o = 16; o; o >>= 1) s += __shfl_xor_sync(0xffffffffu, s, o);
    if (lane == 0) g_ared[row] = s / (float)NN;
}

__global__ void __launch_bounds__(256) k_reduce_b() // 2304 blocks
{
    const int i = blockIdx.x * 256 + threadIdx.x;
    float s = 0.f;
#pragma unroll
    for (int t = 0; t < TT; ++t) s += g_a[(size_t)t * BCN + i];
    g_bred[i] = s / (float)TT;
}

__global__ void __launch_bounds__(256) k_outer(float* __restrict__ out) // 23040 blocks
{
    const int i = blockIdx.x * 256 + threadIdx.x;
    const int n = i % NN;
    const int rest = i / NN;
    const int c = rest % CC;
    const int tb = rest / CC;
    const int b = tb % BB;
    out[i] = g_ared[tb * CC + c] * g_bred[((size_t)b * CC + c) * NN + n];
}

// ---------------------------------------------------------------------------
extern "C" void kernel_launch(void* const* d_in, const int* in_sizes, int n_in,
                              void* d_out, int out_size)
{
    const float* x  = (const float*)d_in[0];
    const float* y  = (const float*)d_in[1];
    const float* sW = (const float*)d_in[2];
    const float* sg = (const float*)d_in[3];
    const float* sb = (const float*)d_in[4];
    const float* tW = (const float*)d_in[5];
    const float* tg = (const float*)d_in[6];
    const float* tbn = (const float*)d_in[7];
    float* out = (float*)d_out;

    dim3 gq(3, 3, 3 * TT * BB); // 120 batch-proj blocks in z
    dim3 gf(3, 3, TT * BB);     // 40

    // ---- spatial path ----
    k_qkv_gemm<<<gq, 256>>>(sW, sg, sb, x, y);
    k_spatial_attn<<<TT * BB * HH, 256>>>();
    k_final_gemm<<<gf, 256>>>(sW + 3 * CC * CC, sg + 3 * CC, sb + 3 * CC);
    k_reduce_a<<<(TT * BB * CC) / 8, 256>>>();

    // ---- temporal path ----
    k_qkv_gemm<<<gq, 256>>>(tW, tg, tbn, x, y);
    k_gather_temporal<<<3 * 480 * 12, 256>>>();
    k_temporal_attn<<<(NN * BB * HH) / 8, 256>>>();
    k_final_gemm<<<gf, 256>>>(tW + 3 * CC * CC, tg + 3 * CC, tbn + 3 * CC);
    k_reduce_b<<<BCN / 256, 256>>>();

    // ---- combine ----
    k_outer<<<TBCN / 256, 256>>>(out);
}